// round 4
// baseline (speedup 1.0000x reference)
#include <cuda_runtime.h>
#include <cuda_fp16.h>
#include <math.h>

// Problem constants (fixed by the dataset)
constexpr int N_NODES = 50000;
constexpr int E_EDGES = 800000;
constexpr int DIN     = 128;      // also H*D_HEAD
constexpr int NHEAD   = 8;
constexpr float INV_SCALE = 0.25f;   // 1/sqrt(16)

// Scratch (device globals — no allocation allowed). Q/K/V stored as fp16
// to halve L2 traffic in the edge phase.
__device__ __half g_Qh[N_NODES * DIN];
__device__ __half g_Kh[N_NODES * DIN];
__device__ __half g_Vh[N_NODES * DIN];
__device__ float  g_z[N_NODES * NHEAD];

// Packed-f32x2 helpers (Blackwell FFMA2 path — only reachable via PTX)
#define PACK_F32X2(out, lo, hi) \
    asm("mov.b64 %0, {%1, %2};" : "=l"(out) : "f"(lo), "f"(hi))
#define FMA_F32X2(d, a, b, c) \
    asm("fma.rn.f32x2 %0, %1, %2, %3;" : "=l"(d) : "l"(a), "l"(b), "l"(c))
#define UNPACK_F32X2(lo, hi, in) \
    asm("mov.b64 {%0, %1}, %2;" : "=f"(lo), "=f"(hi) : "l"(in))

// ---------------------------------------------------------------------------
// Kernel 1: zero the accumulators (d_out is poisoned by the harness)
// ---------------------------------------------------------------------------
__global__ void zero_kernel(float* __restrict__ out)
{
    const int stride = gridDim.x * blockDim.x;
    int i = blockIdx.x * blockDim.x + threadIdx.x;
    float4 zv = make_float4(0.f, 0.f, 0.f, 0.f);
    float4* o4 = reinterpret_cast<float4*>(out);
    float4* z4 = reinterpret_cast<float4*>(g_z);
    constexpr int NOUT4 = N_NODES * DIN / 4;
    constexpr int NZ4   = N_NODES * NHEAD / 4;
    for (int j = i; j < NOUT4; j += stride) o4[j] = zv;
    for (int j = i; j < NZ4;   j += stride) z4[j] = zv;
}

// ---------------------------------------------------------------------------
// Kernel 2: fused QKV GEMM.  C[50000 x 384] = h[50000 x 128] @ {Wq|Wk|Wv}
// blockIdx.y in [0,6): tiles 0-1 -> Q, 2-3 -> K, 4-5 -> V (64 cols each).
// BM=64, BN=64, BK=32, 256 threads.
// Thread tile: 2 rows x 8 cols, accumulators packed as f32x2 along cols.
// Inner loop: 8 x fma.rn.f32x2 per k (FFMA2) instead of 16 x FFMA.
// fp32 math, fp16 stores.
// ---------------------------------------------------------------------------
constexpr int BM = 64, BN = 64, BK = 32;

__global__ __launch_bounds__(256)
void qkv_gemm_kernel(const float* __restrict__ h,
                     const float* __restrict__ Wq, const float* __restrict__ bq,
                     const float* __restrict__ Wk, const float* __restrict__ bk,
                     const float* __restrict__ Wv, const float* __restrict__ bv)
{
    __shared__ float sA[BK][BM];   // transposed h tile
    __shared__ float sB[BK][BN];   // W tile

    const int tid  = threadIdx.x;
    const int row0 = blockIdx.x * BM;
    const int by   = blockIdx.y;

    const float* W    = (by < 2) ? Wq : (by < 4 ? Wk : Wv);
    const float* bias = (by < 2) ? bq : (by < 4 ? bk : bv);
    __half*      outp = (by < 2) ? g_Qh : (by < 4 ? g_Kh : g_Vh);
    const int c0 = (by & 1) * 64;    // column offset within the 128-wide matrix

    const int tr = tid >> 3;   // 0..31 : rows tr*2, tr*2+1
    const int tc = tid & 7;    // 0..7  : cols tc*8 .. tc*8+7

    // acc2[i][j2]: packed pair of fp32 accumulators (cols 2*j2, 2*j2+1)
    unsigned long long acc2[2][4];
#pragma unroll
    for (int i = 0; i < 2; i++)
#pragma unroll
        for (int j = 0; j < 4; j++) acc2[i][j] = 0ull;

    for (int k0 = 0; k0 < DIN; k0 += BK) {
        // load A tile: 64 rows x 32 k, 2 float4 per thread, store transposed
#pragma unroll
        for (int p = 0; p < 2; p++) {
            int r  = p * 32 + (tid >> 3);       // 0..63
            int k4 = (tid & 7) * 4;             // 0..28
            int gr = row0 + r;
            int src = (gr < N_NODES ? gr : N_NODES - 1) * DIN + k0 + k4;
            float4 v = *reinterpret_cast<const float4*>(&h[src]);
            sA[k4 + 0][r] = v.x;
            sA[k4 + 1][r] = v.y;
            sA[k4 + 2][r] = v.z;
            sA[k4 + 3][r] = v.w;
        }
        // load B tile: 32 k x 64 cols, 2 float4 per thread
#pragma unroll
        for (int p = 0; p < 2; p++) {
            int k  = p * 16 + (tid >> 4);       // 0..31
            int c4 = (tid & 15) * 4;            // 0..60
            float4 v = *reinterpret_cast<const float4*>(&W[(k0 + k) * DIN + c0 + c4]);
            *reinterpret_cast<float4*>(&sB[k][c4]) = v;
        }
        __syncthreads();

#pragma unroll
        for (int k = 0; k < BK; k++) {
            float2 a  = *reinterpret_cast<const float2*>(&sA[k][tr * 2]);
            float4 b0 = *reinterpret_cast<const float4*>(&sB[k][tc * 8]);
            float4 b1 = *reinterpret_cast<const float4*>(&sB[k][tc * 8 + 4]);

            unsigned long long ad0, ad1, bp0, bp1, bp2, bp3;
            PACK_F32X2(ad0, a.x, a.x);          // duplicate a-row 0
            PACK_F32X2(ad1, a.y, a.y);          // duplicate a-row 1
            PACK_F32X2(bp0, b0.x, b0.y);        // b packs (aligned pairs, ~free)
            PACK_F32X2(bp1, b0.z, b0.w);
            PACK_F32X2(bp2, b1.x, b1.y);
            PACK_F32X2(bp3, b1.z, b1.w);

            FMA_F32X2(acc2[0][0], ad0, bp0, acc2[0][0]);
            FMA_F32X2(acc2[0][1], ad0, bp1, acc2[0][1]);
            FMA_F32X2(acc2[0][2], ad0, bp2, acc2[0][2]);
            FMA_F32X2(acc2[0][3], ad0, bp3, acc2[0][3]);
            FMA_F32X2(acc2[1][0], ad1, bp0, acc2[1][0]);
            FMA_F32X2(acc2[1][1], ad1, bp1, acc2[1][1]);
            FMA_F32X2(acc2[1][2], ad1, bp2, acc2[1][2]);
            FMA_F32X2(acc2[1][3], ad1, bp3, acc2[1][3]);
        }
        __syncthreads();
    }

    // epilogue: bias + convert to fp16 + store (16 bytes per row)
    float4 bv0 = *reinterpret_cast<const float4*>(&bias[c0 + tc * 8]);
    float4 bv1 = *reinterpret_cast<const float4*>(&bias[c0 + tc * 8 + 4]);
    float bb[8] = {bv0.x, bv0.y, bv0.z, bv0.w, bv1.x, bv1.y, bv1.z, bv1.w};

#pragma unroll
    for (int i = 0; i < 2; i++) {
        int gr = row0 + tr * 2 + i;
        if (gr < N_NODES) {
            float c[8];
#pragma unroll
            for (int j = 0; j < 4; j++) {
                UNPACK_F32X2(c[2 * j], c[2 * j + 1], acc2[i][j]);
            }
            __half2 p0 = __floats2half2_rn(c[0] + bb[0], c[1] + bb[1]);
            __half2 p1 = __floats2half2_rn(c[2] + bb[2], c[3] + bb[3]);
            __half2 p2 = __floats2half2_rn(c[4] + bb[4], c[5] + bb[5]);
            __half2 p3 = __floats2half2_rn(c[6] + bb[6], c[7] + bb[7]);
            uint4 packed;
            packed.x = *reinterpret_cast<unsigned*>(&p0);
            packed.y = *reinterpret_cast<unsigned*>(&p1);
            packed.z = *reinterpret_cast<unsigned*>(&p2);
            packed.w = *reinterpret_cast<unsigned*>(&p3);
            *reinterpret_cast<uint4*>(&outp[gr * DIN + c0 + tc * 8]) = packed;
        }
    }
}

// ---------------------------------------------------------------------------
// Kernel 3: edge scatter. One warp per edge.
// lane l handles elements [4l, 4l+4) of the 128-elem row; head = l>>2.
// fp16 loads (8B per lane per row), fp32 math + fp32 vector red.
// ---------------------------------------------------------------------------
__global__ __launch_bounds__(256)
void edge_kernel(const int* __restrict__ src, const int* __restrict__ dst,
                 float* __restrict__ wV)
{
    const int warp = (blockIdx.x * blockDim.x + threadIdx.x) >> 5;
    const int lane = threadIdx.x & 31;
    if (warp >= E_EDGES) return;

    const int s = src[warp];
    const int d = dst[warp];

    const uint2 kraw = *reinterpret_cast<const uint2*>(&g_Kh[s * DIN + lane * 4]);
    const uint2 qraw = *reinterpret_cast<const uint2*>(&g_Qh[d * DIN + lane * 4]);
    const uint2 vraw = *reinterpret_cast<const uint2*>(&g_Vh[s * DIN + lane * 4]);

    const float2 k0 = __half22float2(*reinterpret_cast<const __half2*>(&kraw.x));
    const float2 k1 = __half22float2(*reinterpret_cast<const __half2*>(&kraw.y));
    const float2 q0 = __half22float2(*reinterpret_cast<const __half2*>(&qraw.x));
    const float2 q1 = __half22float2(*reinterpret_cast<const __half2*>(&qraw.y));

    float part = k0.x * q0.x + k0.y * q0.y + k1.x * q1.x + k1.y * q1.y;
    // reduce over the 4 lanes of this head
    part += __shfl_xor_sync(0xFFFFFFFFu, part, 1);
    part += __shfl_xor_sync(0xFFFFFFFFu, part, 2);

    float x = part * INV_SCALE;
    x = fminf(fmaxf(x, -5.0f), 5.0f);
    const float sc = __expf(x);

    const float2 v0 = __half22float2(*reinterpret_cast<const __half2*>(&vraw.x));
    const float2 v1 = __half22float2(*reinterpret_cast<const __half2*>(&vraw.y));

    float* addr = wV + d * DIN + lane * 4;
    asm volatile("red.global.add.v4.f32 [%0], {%1, %2, %3, %4};"
                 :: "l"(addr),
                    "f"(v0.x * sc), "f"(v0.y * sc), "f"(v1.x * sc), "f"(v1.y * sc)
                 : "memory");

    if ((lane & 3) == 0)
        atomicAdd(&g_z[d * NHEAD + (lane >> 2)], sc);
}

// ---------------------------------------------------------------------------
// Kernel 4: normalize in place: out[i] /= (z[i/16] + 1e-6)
// ---------------------------------------------------------------------------
__global__ void normalize_kernel(float* __restrict__ out)
{
    const int i4 = (blockIdx.x * blockDim.x + threadIdx.x) * 4;
    if (i4 >= N_NODES * DIN) return;
    const float zr = 1.0f / (g_z[i4 >> 4] + 1e-6f);
    float4 v = *reinterpret_cast<float4*>(&out[i4]);
    v.x *= zr; v.y *= zr; v.z *= zr; v.w *= zr;
    *reinterpret_cast<float4*>(&out[i4]) = v;
}

// ---------------------------------------------------------------------------
extern "C" void kernel_launch(void* const* d_in, const int* in_sizes, int n_in,
                              void* d_out, int out_size)
{
    const float* h  = (const float*)d_in[0];
    const float* Wq = (const float*)d_in[1];
    const float* bq = (const float*)d_in[2];
    const float* Wk = (const float*)d_in[3];
    const float* bk = (const float*)d_in[4];
    const float* Wv = (const float*)d_in[5];
    const float* bv = (const float*)d_in[6];
    const int*   src = (const int*)d_in[7];
    const int*   dst = (const int*)d_in[8];
    float* out = (float*)d_out;

    // 1. zero accumulators
    zero_kernel<<<2048, 256>>>(out);

    // 2. fused QKV projection (fp32 f32x2 math, fp16 stores)
    dim3 ggrid((N_NODES + BM - 1) / BM, 6);
    qkv_gemm_kernel<<<ggrid, 256>>>(h, Wq, bq, Wk, bk, Wv, bv);

    // 3. edge scatter: one warp per edge, 8 edges per 256-thread block
    const int eblocks = (E_EDGES + 7) / 8;
    edge_kernel<<<eblocks, 256>>>(src, dst, out);

    // 4. normalize
    const int nthreads4 = N_NODES * DIN / 4;
    normalize_kernel<<<(nthreads4 + 255) / 256, 256>>>(out);
}

// round 5
// speedup vs baseline: 1.6352x; 1.6352x over previous
#include <cuda_runtime.h>
#include <cuda_fp16.h>
#include <math.h>

// Problem constants (fixed by the dataset)
constexpr int N_NODES = 50000;
constexpr int E_EDGES = 800000;
constexpr int DIN     = 128;      // also H*D_HEAD
constexpr int NHEAD   = 8;
constexpr float INV_SCALE = 0.25f;   // 1/sqrt(16)

// Scratch (device globals — no allocation allowed).
__device__ __half g_Qh[N_NODES * DIN];
__device__ __half g_Kh[N_NODES * DIN];
__device__ __half g_Vh[N_NODES * DIN];
// CSR-by-dst structures
__device__ int g_deg[N_NODES];       // in-degree histogram
__device__ int g_cur[N_NODES];       // scatter cursors
__device__ int g_off[N_NODES + 1];   // exclusive prefix (g_off[N] = E)
__device__ int g_esrc[E_EDGES];      // src node per edge, grouped by dst

// ---------------------------------------------------------------------------
// Kernel 1: zero CSR counters (deg + cur). Tiny.
// ---------------------------------------------------------------------------
__global__ void zero_csr_kernel()
{
    int i = blockIdx.x * blockDim.x + threadIdx.x;
    if (i < N_NODES) { g_deg[i] = 0; g_cur[i] = 0; }
}

// ---------------------------------------------------------------------------
// Kernel 2: in-degree histogram
// ---------------------------------------------------------------------------
__global__ void hist_kernel(const int* __restrict__ dst)
{
    const int stride = gridDim.x * blockDim.x;
    for (int i = blockIdx.x * blockDim.x + threadIdx.x; i < E_EDGES; i += stride)
        atomicAdd(&g_deg[dst[i]], 1);
}

// ---------------------------------------------------------------------------
// Kernel 3: exclusive scan of g_deg -> g_off. Single block, 1024 threads,
// 3-level: per-thread serial chunk sum, warp shfl scan, cross-warp combine.
// ---------------------------------------------------------------------------
__global__ __launch_bounds__(1024)
void scan_kernel()
{
    constexpr int CHUNK = (N_NODES + 1023) / 1024;   // 49
    __shared__ int wsum[32];
    const int tid  = threadIdx.x;
    const int lane = tid & 31;
    const int wid  = tid >> 5;
    const int base = tid * CHUNK;

    int sum = 0;
#pragma unroll
    for (int i = 0; i < CHUNK; i++) {
        int idx = base + i;
        if (idx < N_NODES) sum += g_deg[idx];
    }

    // warp-level exclusive scan of per-thread sums
    int incl = sum;
#pragma unroll
    for (int o = 1; o < 32; o <<= 1) {
        int t = __shfl_up_sync(0xFFFFFFFFu, incl, o);
        if (lane >= o) incl += t;
    }
    if (lane == 31) wsum[wid] = incl;
    int excl = incl - sum;
    __syncthreads();

    if (wid == 0) {
        int v = wsum[lane];
        int wi = v;
#pragma unroll
        for (int o = 1; o < 32; o <<= 1) {
            int t = __shfl_up_sync(0xFFFFFFFFu, wi, o);
            if (lane >= o) wi += t;
        }
        wsum[lane] = wi - v;   // exclusive warp offsets
    }
    __syncthreads();

    int run = wsum[wid] + excl;
#pragma unroll
    for (int i = 0; i < CHUNK; i++) {
        int idx = base + i;
        if (idx < N_NODES) {
            g_off[idx] = run;
            run += g_deg[idx];
        }
    }
    if (tid == 0) g_off[N_NODES] = E_EDGES;
}

// ---------------------------------------------------------------------------
// Kernel 4: scatter src ids into CSR order
// ---------------------------------------------------------------------------
__global__ void scatter_kernel(const int* __restrict__ src,
                               const int* __restrict__ dst)
{
    const int stride = gridDim.x * blockDim.x;
    for (int i = blockIdx.x * blockDim.x + threadIdx.x; i < E_EDGES; i += stride) {
        const int d = dst[i];
        const int p = atomicAdd(&g_cur[d], 1);
        g_esrc[g_off[d] + p] = src[i];
    }
}

// ---------------------------------------------------------------------------
// Kernel 5: fused QKV GEMM (R3 scalar-FFMA version, known-good 136us).
// C[50000 x 384] = h[50000 x 128] @ {Wq|Wk|Wv}, fp32 math, fp16 stores.
// ---------------------------------------------------------------------------
constexpr int BM = 64, BN = 64, BK = 32;

__global__ __launch_bounds__(256)
void qkv_gemm_kernel(const float* __restrict__ h,
                     const float* __restrict__ Wq, const float* __restrict__ bq,
                     const float* __restrict__ Wk, const float* __restrict__ bk,
                     const float* __restrict__ Wv, const float* __restrict__ bv)
{
    __shared__ float sA[BK][BM];   // transposed h tile
    __shared__ float sB[BK][BN];   // W tile

    const int tid  = threadIdx.x;
    const int row0 = blockIdx.x * BM;
    const int by   = blockIdx.y;

    const float* W    = (by < 2) ? Wq : (by < 4 ? Wk : Wv);
    const float* bias = (by < 2) ? bq : (by < 4 ? bk : bv);
    __half*      outp = (by < 2) ? g_Qh : (by < 4 ? g_Kh : g_Vh);
    const int c0 = (by & 1) * 64;

    const int tr = tid >> 4;   // 0..15
    const int tc = tid & 15;   // 0..15

    float acc[4][4];
#pragma unroll
    for (int i = 0; i < 4; i++)
#pragma unroll
        for (int j = 0; j < 4; j++) acc[i][j] = 0.f;

    for (int k0 = 0; k0 < DIN; k0 += BK) {
#pragma unroll
        for (int p = 0; p < 2; p++) {
            int r  = p * 32 + (tid >> 3);
            int k4 = (tid & 7) * 4;
            int gr = row0 + r;
            int src = (gr < N_NODES ? gr : N_NODES - 1) * DIN + k0 + k4;
            float4 v = *reinterpret_cast<const float4*>(&h[src]);
            sA[k4 + 0][r] = v.x;
            sA[k4 + 1][r] = v.y;
            sA[k4 + 2][r] = v.z;
            sA[k4 + 3][r] = v.w;
        }
#pragma unroll
        for (int p = 0; p < 2; p++) {
            int k  = p * 16 + (tid >> 4);
            int c4 = (tid & 15) * 4;
            float4 v = *reinterpret_cast<const float4*>(&W[(k0 + k) * DIN + c0 + c4]);
            *reinterpret_cast<float4*>(&sB[k][c4]) = v;
        }
        __syncthreads();

#pragma unroll
        for (int k = 0; k < BK; k++) {
            float4 a = *reinterpret_cast<const float4*>(&sA[k][tr * 4]);
            float4 b = *reinterpret_cast<const float4*>(&sB[k][tc * 4]);
            float av[4] = {a.x, a.y, a.z, a.w};
            float bv4[4] = {b.x, b.y, b.z, b.w};
#pragma unroll
            for (int i = 0; i < 4; i++)
#pragma unroll
                for (int j = 0; j < 4; j++) acc[i][j] += av[i] * bv4[j];
        }
        __syncthreads();
    }

    float4 bvv = *reinterpret_cast<const float4*>(&bias[c0 + tc * 4]);
    float bb[4] = {bvv.x, bvv.y, bvv.z, bvv.w};
#pragma unroll
    for (int i = 0; i < 4; i++) {
        int gr = row0 + tr * 4 + i;
        if (gr < N_NODES) {
            __half2 lo = __floats2half2_rn(acc[i][0] + bb[0], acc[i][1] + bb[1]);
            __half2 hi = __floats2half2_rn(acc[i][2] + bb[2], acc[i][3] + bb[3]);
            uint2 packed;
            packed.x = *reinterpret_cast<unsigned*>(&lo);
            packed.y = *reinterpret_cast<unsigned*>(&hi);
            *reinterpret_cast<uint2*>(&outp[gr * DIN + c0 + tc * 4]) = packed;
        }
    }
}

// ---------------------------------------------------------------------------
// Kernel 6: CSR gather. One warp per destination node. No atomics.
// lane l owns elements [4l, 4l+4) of the 128-elem row; head = l>>2.
// Q[dst] row stays in registers; per edge: load K[src],V[src], dot via shfl,
// accumulate wV and z in registers; fused normalize on the single write.
// ---------------------------------------------------------------------------
__device__ __forceinline__ void gather_edge(
    int s, int lane, const float2& q0, const float2& q1,
    float& a0, float& a1, float& a2, float& a3, float& zsum)
{
    const uint2 kraw = *reinterpret_cast<const uint2*>(&g_Kh[s * DIN + lane * 4]);
    const float2 k0 = __half22float2(*reinterpret_cast<const __half2*>(&kraw.x));
    const float2 k1 = __half22float2(*reinterpret_cast<const __half2*>(&kraw.y));

    float part = k0.x * q0.x + k0.y * q0.y + k1.x * q1.x + k1.y * q1.y;
    part += __shfl_xor_sync(0xFFFFFFFFu, part, 1);
    part += __shfl_xor_sync(0xFFFFFFFFu, part, 2);

    float x = part * INV_SCALE;
    x = fminf(fmaxf(x, -5.0f), 5.0f);
    const float sc = __expf(x);

    const uint2 vraw = *reinterpret_cast<const uint2*>(&g_Vh[s * DIN + lane * 4]);
    const float2 v0 = __half22float2(*reinterpret_cast<const __half2*>(&vraw.x));
    const float2 v1 = __half22float2(*reinterpret_cast<const __half2*>(&vraw.y));

    a0 += v0.x * sc;
    a1 += v0.y * sc;
    a2 += v1.x * sc;
    a3 += v1.y * sc;
    zsum += sc;          // identical across the 4 lanes of a head
}

__global__ __launch_bounds__(256)
void gather_kernel(float* __restrict__ out)
{
    const int node = (blockIdx.x * blockDim.x + threadIdx.x) >> 5;
    const int lane = threadIdx.x & 31;
    if (node >= N_NODES) return;

    const uint2 qraw = *reinterpret_cast<const uint2*>(&g_Qh[node * DIN + lane * 4]);
    const float2 q0 = __half22float2(*reinterpret_cast<const __half2*>(&qraw.x));
    const float2 q1 = __half22float2(*reinterpret_cast<const __half2*>(&qraw.y));

    const int j0 = g_off[node];
    const int j1 = g_off[node + 1];

    float a0 = 0.f, a1 = 0.f, a2 = 0.f, a3 = 0.f, zsum = 0.f;

    int j = j0;
    // unroll-2 for MLP on the K/V loads
    for (; j + 1 < j1; j += 2) {
        const int sa = g_esrc[j];
        const int sb = g_esrc[j + 1];
        gather_edge(sa, lane, q0, q1, a0, a1, a2, a3, zsum);
        gather_edge(sb, lane, q0, q1, a0, a1, a2, a3, zsum);
    }
    if (j < j1) {
        gather_edge(g_esrc[j], lane, q0, q1, a0, a1, a2, a3, zsum);
    }

    const float zr = 1.0f / (zsum + 1e-6f);
    float4 o;
    o.x = a0 * zr; o.y = a1 * zr; o.z = a2 * zr; o.w = a3 * zr;
    *reinterpret_cast<float4*>(&out[node * DIN + lane * 4]) = o;
}

// ---------------------------------------------------------------------------
extern "C" void kernel_launch(void* const* d_in, const int* in_sizes, int n_in,
                              void* d_out, int out_size)
{
    const float* h  = (const float*)d_in[0];
    const float* Wq = (const float*)d_in[1];
    const float* bq = (const float*)d_in[2];
    const float* Wk = (const float*)d_in[3];
    const float* bk = (const float*)d_in[4];
    const float* Wv = (const float*)d_in[5];
    const float* bv = (const float*)d_in[6];
    const int*   src = (const int*)d_in[7];
    const int*   dst = (const int*)d_in[8];
    float* out = (float*)d_out;

    // CSR build
    zero_csr_kernel<<<(N_NODES + 255) / 256, 256>>>();
    hist_kernel<<<1184, 256>>>(dst);
    scan_kernel<<<1, 1024>>>();
    scatter_kernel<<<1184, 256>>>(src, dst);

    // fused QKV projection (fp32 math, fp16 stores)
    dim3 ggrid((N_NODES + BM - 1) / BM, 6);
    qkv_gemm_kernel<<<ggrid, 256>>>(h, Wq, bq, Wk, bk, Wv, bv);

    // CSR gather: one warp per node, 8 nodes per 256-thread block
    gather_kernel<<<(N_NODES + 7) / 8, 256>>>(out);
}

// round 6
// speedup vs baseline: 2.6496x; 1.6203x over previous
#include <cuda_runtime.h>
#include <cuda_fp16.h>
#include <math.h>

// Problem constants (fixed by the dataset)
constexpr int N_NODES = 50000;
constexpr int E_EDGES = 800000;
constexpr int DIN     = 128;      // also H*D_HEAD
constexpr int NHEAD   = 8;
constexpr float INV_SCALE = 0.25f;   // 1/sqrt(16)

// Scratch (device globals — no allocation allowed).
__device__ __half g_hh[N_NODES * DIN];        // h in fp16
__device__ __half g_Wh[3 * DIN * DIN];        // Wq|Wk|Wv in fp16
__device__ __half g_Qh[N_NODES * DIN];
__device__ __half g_Kh[N_NODES * DIN];
__device__ __half g_Vh[N_NODES * DIN];
// CSR-by-dst structures
__device__ int g_deg[N_NODES];
__device__ int g_cur[N_NODES];
__device__ int g_off[N_NODES + 1];
__device__ int g_esrc[E_EDGES];

// ---------------------------------------------------------------------------
// Converters: fp32 -> fp16
// ---------------------------------------------------------------------------
__global__ void convert_h_kernel(const float* __restrict__ h)
{
    const int i = (blockIdx.x * blockDim.x + threadIdx.x) * 4;
    if (i >= N_NODES * DIN) return;
    float4 v = *reinterpret_cast<const float4*>(&h[i]);
    __half2 lo = __floats2half2_rn(v.x, v.y);
    __half2 hi = __floats2half2_rn(v.z, v.w);
    uint2 p;
    p.x = *reinterpret_cast<unsigned*>(&lo);
    p.y = *reinterpret_cast<unsigned*>(&hi);
    *reinterpret_cast<uint2*>(&g_hh[i]) = p;
}

__global__ void convert_w_kernel(const float* __restrict__ Wq,
                                 const float* __restrict__ Wk,
                                 const float* __restrict__ Wv)
{
    const int i = (blockIdx.x * blockDim.x + threadIdx.x) * 4;
    if (i >= 3 * DIN * DIN) return;
    const int mat = i >> 14;             // /16384
    const int off = i & 16383;
    const float* W = (mat == 0) ? Wq : (mat == 1 ? Wk : Wv);
    float4 v = *reinterpret_cast<const float4*>(&W[off]);
    __half2 lo = __floats2half2_rn(v.x, v.y);
    __half2 hi = __floats2half2_rn(v.z, v.w);
    uint2 p;
    p.x = *reinterpret_cast<unsigned*>(&lo);
    p.y = *reinterpret_cast<unsigned*>(&hi);
    *reinterpret_cast<uint2*>(&g_Wh[i]) = p;
}

// ---------------------------------------------------------------------------
// CSR build: zero, histogram, scan, scatter
// ---------------------------------------------------------------------------
__global__ void zero_csr_kernel()
{
    int i = blockIdx.x * blockDim.x + threadIdx.x;
    if (i < N_NODES) { g_deg[i] = 0; g_cur[i] = 0; }
}

__global__ void hist_kernel(const int* __restrict__ dst)
{
    const int stride = gridDim.x * blockDim.x;
    for (int i = blockIdx.x * blockDim.x + threadIdx.x; i < E_EDGES; i += stride)
        atomicAdd(&g_deg[dst[i]], 1);
}

__global__ __launch_bounds__(1024)
void scan_kernel()
{
    constexpr int CHUNK = (N_NODES + 1023) / 1024;   // 49
    __shared__ int wsum[32];
    const int tid  = threadIdx.x;
    const int lane = tid & 31;
    const int wid  = tid >> 5;
    const int base = tid * CHUNK;

    int sum = 0;
#pragma unroll
    for (int i = 0; i < CHUNK; i++) {
        int idx = base + i;
        if (idx < N_NODES) sum += g_deg[idx];
    }
    int incl = sum;
#pragma unroll
    for (int o = 1; o < 32; o <<= 1) {
        int t = __shfl_up_sync(0xFFFFFFFFu, incl, o);
        if (lane >= o) incl += t;
    }
    if (lane == 31) wsum[wid] = incl;
    int excl = incl - sum;
    __syncthreads();
    if (wid == 0) {
        int v = wsum[lane];
        int wi = v;
#pragma unroll
        for (int o = 1; o < 32; o <<= 1) {
            int t = __shfl_up_sync(0xFFFFFFFFu, wi, o);
            if (lane >= o) wi += t;
        }
        wsum[lane] = wi - v;
    }
    __syncthreads();
    int run = wsum[wid] + excl;
#pragma unroll
    for (int i = 0; i < CHUNK; i++) {
        int idx = base + i;
        if (idx < N_NODES) {
            g_off[idx] = run;
            run += g_deg[idx];
        }
    }
    if (tid == 0) g_off[N_NODES] = E_EDGES;
}

__global__ void scatter_kernel(const int* __restrict__ src,
                               const int* __restrict__ dst)
{
    const int stride = gridDim.x * blockDim.x;
    for (int i = blockIdx.x * blockDim.x + threadIdx.x; i < E_EDGES; i += stride) {
        const int d = dst[i];
        const int p = atomicAdd(&g_cur[d], 1);
        g_esrc[g_off[d] + p] = src[i];
    }
}

// ---------------------------------------------------------------------------
// Tensor-core QKV GEMM: C[50000x128] = h_fp16 @ W_fp16 (+bias), per Q/K/V.
// mma.sync.m16n8k16 fp16 in / fp32 acc. BM=64 rows, BN=64 cols per block.
// grid = (ceil(N/64), 6): y/2 selects matrix, y&1 selects column half.
// 8 warps: 4 along M (16 rows each) x 2 along N (32 cols each).
// ---------------------------------------------------------------------------
constexpr int GBM = 64;
constexpr int LDA = 136;   // smem stride (halves): 272B -> +4 banks/row
constexpr int LDB = 72;    // smem stride (halves): 144B -> +4 banks/row

__global__ __launch_bounds__(256)
void qkv_hmma_kernel(const float* __restrict__ bq,
                     const float* __restrict__ bk,
                     const float* __restrict__ bv)
{
    __shared__ __half sA[GBM * LDA];       // 64 x 128 (k)
    __shared__ __half sB[DIN * LDB];       // 128 (k) x 64 (n)

    const int tid  = threadIdx.x;
    const int lane = tid & 31;
    const int wid  = tid >> 5;
    const int row0 = blockIdx.x * GBM;
    const int by   = blockIdx.y;
    const int mat  = by >> 1;              // 0=Q, 1=K, 2=V
    const int n0   = (by & 1) * 64;        // global column offset

    const float* bias = (mat == 0) ? bq : (mat == 1 ? bk : bv);
    __half*      outp = (mat == 0) ? g_Qh : (mat == 1 ? g_Kh : g_Vh);
    const __half* Wp  = g_Wh + mat * DIN * DIN;

    // --- load A tile: 64 rows x 128 halves, 16B chunks ---
#pragma unroll
    for (int p = 0; p < 4; p++) {
        int c   = tid + p * 256;           // 0..1023
        int r   = c >> 4;                  // 0..63
        int cc  = (c & 15) << 3;           // half offset 0..120
        int gr  = row0 + r;
        if (gr >= N_NODES) gr = N_NODES - 1;
        uint4 v = *reinterpret_cast<const uint4*>(&g_hh[gr * DIN + cc]);
        *reinterpret_cast<uint4*>(&sA[r * LDA + cc]) = v;
    }
    // --- load B tile: 128 k-rows x 64 halves ---
#pragma unroll
    for (int p = 0; p < 4; p++) {
        int c  = tid + p * 256;            // 0..1023
        int r  = c >> 3;                   // 0..127
        int cc = (c & 7) << 3;             // 0..56
        uint4 v = *reinterpret_cast<const uint4*>(&Wp[r * DIN + n0 + cc]);
        *reinterpret_cast<uint4*>(&sB[r * LDB + cc]) = v;
    }
    __syncthreads();

    const int wm = (wid & 3) * 16;         // warp row offset in tile
    const int wn = (wid >> 2) * 32;        // warp col offset in tile

    float acc[4][4];                       // 4 n-tiles x 4 regs
#pragma unroll
    for (int t = 0; t < 4; t++)
#pragma unroll
        for (int r = 0; r < 4; r++) acc[t][r] = 0.f;

    // smem byte addresses for ldmatrix
    const unsigned aBase = (unsigned)__cvta_generic_to_shared(sA);
    const unsigned bBase = (unsigned)__cvta_generic_to_shared(sB);

#pragma unroll
    for (int ks = 0; ks < 8; ks++) {
        const int k0 = ks * 16;
        // A fragment: 16x16 at (wm, k0)
        unsigned a0, a1, a2, a3;
        {
            unsigned addr = aBase +
                ((wm + (lane & 15)) * LDA + k0 + ((lane >> 4) << 3)) * 2;
            asm volatile(
                "ldmatrix.sync.aligned.m8n8.x4.shared.b16 {%0,%1,%2,%3}, [%4];"
                : "=r"(a0), "=r"(a1), "=r"(a2), "=r"(a3) : "r"(addr));
        }
        // B fragments: two x4.trans loads cover 4 n-tiles of 8
#pragma unroll
        for (int hf = 0; hf < 2; hf++) {
            const int nw = wn + hf * 16;
            unsigned b0, b1, b2, b3;
            unsigned addr = bBase +
                ((k0 + (lane & 15)) * LDB + nw + ((lane >> 4) << 3)) * 2;
            asm volatile(
                "ldmatrix.sync.aligned.m8n8.x4.trans.shared.b16 {%0,%1,%2,%3}, [%4];"
                : "=r"(b0), "=r"(b1), "=r"(b2), "=r"(b3) : "r"(addr));
            const int t0 = hf * 2;
            asm volatile(
                "mma.sync.aligned.m16n8k16.row.col.f32.f16.f16.f32 "
                "{%0,%1,%2,%3}, {%4,%5,%6,%7}, {%8,%9}, {%0,%1,%2,%3};"
                : "+f"(acc[t0][0]), "+f"(acc[t0][1]), "+f"(acc[t0][2]), "+f"(acc[t0][3])
                : "r"(a0), "r"(a1), "r"(a2), "r"(a3), "r"(b0), "r"(b1));
            asm volatile(
                "mma.sync.aligned.m16n8k16.row.col.f32.f16.f16.f32 "
                "{%0,%1,%2,%3}, {%4,%5,%6,%7}, {%8,%9}, {%0,%1,%2,%3};"
                : "+f"(acc[t0+1][0]), "+f"(acc[t0+1][1]), "+f"(acc[t0+1][2]), "+f"(acc[t0+1][3])
                : "r"(a0), "r"(a1), "r"(a2), "r"(a3), "r"(b2), "r"(b3));
        }
    }

    // epilogue: d0,d1 -> row lane/4, cols 2*(lane%4)(+1); d2,d3 -> row+8
    const int rr = lane >> 2;
    const int cc2 = (lane & 3) * 2;
#pragma unroll
    for (int t = 0; t < 4; t++) {
        const int gc = n0 + wn + t * 8 + cc2;          // global col
        const float b0f = bias[gc], b1f = bias[gc + 1];
        int gr0 = row0 + wm + rr;
        int gr1 = gr0 + 8;
        if (gr0 < N_NODES) {
            __half2 h2 = __floats2half2_rn(acc[t][0] + b0f, acc[t][1] + b1f);
            *reinterpret_cast<unsigned*>(&outp[gr0 * DIN + gc]) =
                *reinterpret_cast<unsigned*>(&h2);
        }
        if (gr1 < N_NODES) {
            __half2 h2 = __floats2half2_rn(acc[t][2] + b0f, acc[t][3] + b1f);
            *reinterpret_cast<unsigned*>(&outp[gr1 * DIN + gc]) =
                *reinterpret_cast<unsigned*>(&h2);
        }
    }
}

// ---------------------------------------------------------------------------
// CSR gather. One warp per destination node. Batch-4 edges for MLP.
// lane l owns elements [4l, 4l+4); head = l>>2.
// ---------------------------------------------------------------------------
__device__ __forceinline__ void edge_math(
    const uint2& kraw, const uint2& vraw, int lane,
    const float2& q0, const float2& q1,
    float& a0, float& a1, float& a2, float& a3, float& zsum)
{
    const float2 k0 = __half22float2(*reinterpret_cast<const __half2*>(&kraw.x));
    const float2 k1 = __half22float2(*reinterpret_cast<const __half2*>(&kraw.y));

    float part = k0.x * q0.x + k0.y * q0.y + k1.x * q1.x + k1.y * q1.y;
    part += __shfl_xor_sync(0xFFFFFFFFu, part, 1);
    part += __shfl_xor_sync(0xFFFFFFFFu, part, 2);

    float x = part * INV_SCALE;
    x = fminf(fmaxf(x, -5.0f), 5.0f);
    const float sc = __expf(x);

    const float2 v0 = __half22float2(*reinterpret_cast<const __half2*>(&vraw.x));
    const float2 v1 = __half22float2(*reinterpret_cast<const __half2*>(&vraw.y));

    a0 += v0.x * sc; a1 += v0.y * sc; a2 += v1.x * sc; a3 += v1.y * sc;
    zsum += sc;
}

__global__ __launch_bounds__(256)
void gather_kernel(float* __restrict__ out)
{
    const int node = (blockIdx.x * blockDim.x + threadIdx.x) >> 5;
    const int lane = threadIdx.x & 31;
    if (node >= N_NODES) return;

    const uint2 qraw = *reinterpret_cast<const uint2*>(&g_Qh[node * DIN + lane * 4]);
    const float2 q0 = __half22float2(*reinterpret_cast<const __half2*>(&qraw.x));
    const float2 q1 = __half22float2(*reinterpret_cast<const __half2*>(&qraw.y));

    const int j0 = g_off[node];
    const int j1 = g_off[node + 1];

    float a0 = 0.f, a1 = 0.f, a2 = 0.f, a3 = 0.f, zsum = 0.f;

    int j = j0;
    for (; j + 4 <= j1; j += 4) {
        const int s0 = g_esrc[j + 0];
        const int s1 = g_esrc[j + 1];
        const int s2 = g_esrc[j + 2];
        const int s3 = g_esrc[j + 3];
        // issue all 8 row loads before any dependent math (MLP=8)
        const uint2 k0r = *reinterpret_cast<const uint2*>(&g_Kh[s0 * DIN + lane * 4]);
        const uint2 k1r = *reinterpret_cast<const uint2*>(&g_Kh[s1 * DIN + lane * 4]);
        const uint2 k2r = *reinterpret_cast<const uint2*>(&g_Kh[s2 * DIN + lane * 4]);
        const uint2 k3r = *reinterpret_cast<const uint2*>(&g_Kh[s3 * DIN + lane * 4]);
        const uint2 v0r = *reinterpret_cast<const uint2*>(&g_Vh[s0 * DIN + lane * 4]);
        const uint2 v1r = *reinterpret_cast<const uint2*>(&g_Vh[s1 * DIN + lane * 4]);
        const uint2 v2r = *reinterpret_cast<const uint2*>(&g_Vh[s2 * DIN + lane * 4]);
        const uint2 v3r = *reinterpret_cast<const uint2*>(&g_Vh[s3 * DIN + lane * 4]);
        edge_math(k0r, v0r, lane, q0, q1, a0, a1, a2, a3, zsum);
        edge_math(k1r, v1r, lane, q0, q1, a0, a1, a2, a3, zsum);
        edge_math(k2r, v2r, lane, q0, q1, a0, a1, a2, a3, zsum);
        edge_math(k3r, v3r, lane, q0, q1, a0, a1, a2, a3, zsum);
    }
    for (; j < j1; j++) {
        const int s = g_esrc[j];
        const uint2 kr = *reinterpret_cast<const uint2*>(&g_Kh[s * DIN + lane * 4]);
        const uint2 vr = *reinterpret_cast<const uint2*>(&g_Vh[s * DIN + lane * 4]);
        edge_math(kr, vr, lane, q0, q1, a0, a1, a2, a3, zsum);
    }

    const float zr = 1.0f / (zsum + 1e-6f);
    float4 o;
    o.x = a0 * zr; o.y = a1 * zr; o.z = a2 * zr; o.w = a3 * zr;
    *reinterpret_cast<float4*>(&out[node * DIN + lane * 4]) = o;
}

// ---------------------------------------------------------------------------
extern "C" void kernel_launch(void* const* d_in, const int* in_sizes, int n_in,
                              void* d_out, int out_size)
{
    const float* h  = (const float*)d_in[0];
    const float* Wq = (const float*)d_in[1];
    const float* bq = (const float*)d_in[2];
    const float* Wk = (const float*)d_in[3];
    const float* bk = (const float*)d_in[4];
    const float* Wv = (const float*)d_in[5];
    const float* bv = (const float*)d_in[6];
    const int*   src = (const int*)d_in[7];
    const int*   dst = (const int*)d_in[8];
    float* out = (float*)d_out;

    // fp16 conversions
    convert_h_kernel<<<(N_NODES * DIN / 4 + 255) / 256, 256>>>(h);
    convert_w_kernel<<<(3 * DIN * DIN / 4 + 255) / 256, 256>>>(Wq, Wk, Wv);

    // CSR build
    zero_csr_kernel<<<(N_NODES + 255) / 256, 256>>>();
    hist_kernel<<<1184, 256>>>(dst);
    scan_kernel<<<1, 1024>>>();
    scatter_kernel<<<1184, 256>>>(src, dst);

    // tensor-core QKV projection
    dim3 ggrid((N_NODES + GBM - 1) / GBM, 6);
    qkv_hmma_kernel<<<ggrid, 256>>>(bq, bk, bv);

    // CSR gather: one warp per node
    gather_kernel<<<(N_NODES + 7) / 8, 256>>>(out);
}

// round 7
// speedup vs baseline: 3.2704x; 1.2343x over previous
#include <cuda_runtime.h>
#include <cuda_fp16.h>
#include <math.h>

// Problem constants (fixed by the dataset)
constexpr int N_NODES = 50000;
constexpr int E_EDGES = 800000;
constexpr int DIN     = 128;      // also H*D_HEAD
constexpr int NHEAD   = 8;
constexpr float INV_SCALE = 0.25f;   // 1/sqrt(16)

// Scratch (device globals — no allocation allowed).
__device__ __half g_hh[N_NODES * DIN];        // h in fp16
__device__ __half g_Wh[3 * DIN * DIN];        // Wq|Wk|Wv in fp16
__device__ __half g_Qh[N_NODES * DIN];
__device__ __half g_Kh[N_NODES * DIN];
__device__ __half g_Vh[N_NODES * DIN];
// CSR-by-dst structures
__device__ int g_deg[N_NODES];
__device__ int g_cur[N_NODES];
__device__ int g_off[N_NODES + 1];
__device__ int g_esrc[E_EDGES];

// ---------------------------------------------------------------------------
// Converters: fp32 -> fp16
// ---------------------------------------------------------------------------
__global__ void convert_h_kernel(const float* __restrict__ h)
{
    const int i = (blockIdx.x * blockDim.x + threadIdx.x) * 4;
    if (i >= N_NODES * DIN) return;
    float4 v = *reinterpret_cast<const float4*>(&h[i]);
    __half2 lo = __floats2half2_rn(v.x, v.y);
    __half2 hi = __floats2half2_rn(v.z, v.w);
    uint2 p;
    p.x = *reinterpret_cast<unsigned*>(&lo);
    p.y = *reinterpret_cast<unsigned*>(&hi);
    *reinterpret_cast<uint2*>(&g_hh[i]) = p;
}

__global__ void convert_w_kernel(const float* __restrict__ Wq,
                                 const float* __restrict__ Wk,
                                 const float* __restrict__ Wv)
{
    const int i = (blockIdx.x * blockDim.x + threadIdx.x) * 4;
    if (i >= 3 * DIN * DIN) return;
    const int mat = i >> 14;             // /16384
    const int off = i & 16383;
    const float* W = (mat == 0) ? Wq : (mat == 1 ? Wk : Wv);
    float4 v = *reinterpret_cast<const float4*>(&W[off]);
    __half2 lo = __floats2half2_rn(v.x, v.y);
    __half2 hi = __floats2half2_rn(v.z, v.w);
    uint2 p;
    p.x = *reinterpret_cast<unsigned*>(&lo);
    p.y = *reinterpret_cast<unsigned*>(&hi);
    *reinterpret_cast<uint2*>(&g_Wh[i]) = p;
}

// ---------------------------------------------------------------------------
// CSR build
// ---------------------------------------------------------------------------
__global__ void zero_deg_kernel()
{
    int i = blockIdx.x * blockDim.x + threadIdx.x;
    if (i < N_NODES) g_deg[i] = 0;
}

__global__ void hist_kernel(const int* __restrict__ dst)
{
    const int stride = gridDim.x * blockDim.x;
    for (int i = blockIdx.x * blockDim.x + threadIdx.x; i < E_EDGES; i += stride)
        atomicAdd(&g_deg[dst[i]], 1);
}

// Coalesced single-block scan. Warp w owns region [w*1568, (w+1)*1568);
// lane l accesses base + 32*i + l  -> every LDG/STG hits one 128B line.
// Also seeds g_cur = g_off so scatter needs no extra g_off load.
__global__ __launch_bounds__(1024)
void scan_kernel()
{
    constexpr int WREG  = 1568;            // 49 * 32, 32 warps cover 50176 >= N
    constexpr int ITERS = WREG / 32;       // 49
    __shared__ int warpTot[32];

    const int tid  = threadIdx.x;
    const int lane = tid & 31;
    const int w    = tid >> 5;
    const int base = w * WREG;

    // pass 1: per-warp region sum (coalesced)
    int s = 0;
#pragma unroll
    for (int i = 0; i < ITERS; i++) {
        int idx = base + i * 32 + lane;
        if (idx < N_NODES) s += g_deg[idx];
    }
#pragma unroll
    for (int o = 16; o > 0; o >>= 1)
        s += __shfl_xor_sync(0xFFFFFFFFu, s, o);
    if (lane == 0) warpTot[w] = s;
    __syncthreads();

    // warp 0: exclusive scan of the 32 warp totals
    if (w == 0) {
        int v = warpTot[lane];
        int p = v;
#pragma unroll
        for (int o = 1; o < 32; o <<= 1) {
            int t = __shfl_up_sync(0xFFFFFFFFu, p, o);
            if (lane >= o) p += t;
        }
        warpTot[lane] = p - v;
    }
    __syncthreads();

    // pass 2: running stripe scan (coalesced loads + stores)
    int carry = warpTot[w];
#pragma unroll
    for (int i = 0; i < ITERS; i++) {
        int idx = base + i * 32 + lane;
        int v = (idx < N_NODES) ? g_deg[idx] : 0;
        int incl = v;
#pragma unroll
        for (int o = 1; o < 32; o <<= 1) {
            int t = __shfl_up_sync(0xFFFFFFFFu, incl, o);
            if (lane >= o) incl += t;
        }
        if (idx < N_NODES) {
            int e = carry + incl - v;
            g_off[idx] = e;
            g_cur[idx] = e;          // seed scatter cursor
        }
        carry += __shfl_sync(0xFFFFFFFFu, incl, 31);
    }
    if (tid == 0) g_off[N_NODES] = E_EDGES;
}

// scatter src ids into CSR order (cursor pre-seeded with offsets)
__global__ void scatter_kernel(const int* __restrict__ src,
                               const int* __restrict__ dst)
{
    const int stride = gridDim.x * blockDim.x;
    for (int i = blockIdx.x * blockDim.x + threadIdx.x; i < E_EDGES; i += stride) {
        const int p = atomicAdd(&g_cur[dst[i]], 1);
        g_esrc[p] = src[i];
    }
}

// ---------------------------------------------------------------------------
// Tensor-core QKV GEMM: C[50000x128] = h_fp16 @ W_fp16 (+bias), per Q/K/V.
// mma.sync.m16n8k16 fp16 in / fp32 acc. BM=64 rows, BN=64 cols per block.
// ---------------------------------------------------------------------------
constexpr int GBM = 64;
constexpr int LDA = 136;   // smem stride (halves)
constexpr int LDB = 72;

__global__ __launch_bounds__(256)
void qkv_hmma_kernel(const float* __restrict__ bq,
                     const float* __restrict__ bk,
                     const float* __restrict__ bv)
{
    __shared__ __half sA[GBM * LDA];       // 64 x 128 (k)
    __shared__ __half sB[DIN * LDB];       // 128 (k) x 64 (n)

    const int tid  = threadIdx.x;
    const int lane = tid & 31;
    const int wid  = tid >> 5;
    const int row0 = blockIdx.x * GBM;
    const int by   = blockIdx.y;
    const int mat  = by >> 1;              // 0=Q, 1=K, 2=V
    const int n0   = (by & 1) * 64;

    const float* bias = (mat == 0) ? bq : (mat == 1 ? bk : bv);
    __half*      outp = (mat == 0) ? g_Qh : (mat == 1 ? g_Kh : g_Vh);
    const __half* Wp  = g_Wh + mat * DIN * DIN;

#pragma unroll
    for (int p = 0; p < 4; p++) {
        int c   = tid + p * 256;
        int r   = c >> 4;
        int cc  = (c & 15) << 3;
        int gr  = row0 + r;
        if (gr >= N_NODES) gr = N_NODES - 1;
        uint4 v = *reinterpret_cast<const uint4*>(&g_hh[gr * DIN + cc]);
        *reinterpret_cast<uint4*>(&sA[r * LDA + cc]) = v;
    }
#pragma unroll
    for (int p = 0; p < 4; p++) {
        int c  = tid + p * 256;
        int r  = c >> 3;
        int cc = (c & 7) << 3;
        uint4 v = *reinterpret_cast<const uint4*>(&Wp[r * DIN + n0 + cc]);
        *reinterpret_cast<uint4*>(&sB[r * LDB + cc]) = v;
    }
    __syncthreads();

    const int wm = (wid & 3) * 16;
    const int wn = (wid >> 2) * 32;

    float acc[4][4];
#pragma unroll
    for (int t = 0; t < 4; t++)
#pragma unroll
        for (int r = 0; r < 4; r++) acc[t][r] = 0.f;

    const unsigned aBase = (unsigned)__cvta_generic_to_shared(sA);
    const unsigned bBase = (unsigned)__cvta_generic_to_shared(sB);

#pragma unroll
    for (int ks = 0; ks < 8; ks++) {
        const int k0 = ks * 16;
        unsigned a0, a1, a2, a3;
        {
            unsigned addr = aBase +
                ((wm + (lane & 15)) * LDA + k0 + ((lane >> 4) << 3)) * 2;
            asm volatile(
                "ldmatrix.sync.aligned.m8n8.x4.shared.b16 {%0,%1,%2,%3}, [%4];"
                : "=r"(a0), "=r"(a1), "=r"(a2), "=r"(a3) : "r"(addr));
        }
#pragma unroll
        for (int hf = 0; hf < 2; hf++) {
            const int nw = wn + hf * 16;
            unsigned b0, b1, b2, b3;
            unsigned addr = bBase +
                ((k0 + (lane & 15)) * LDB + nw + ((lane >> 4) << 3)) * 2;
            asm volatile(
                "ldmatrix.sync.aligned.m8n8.x4.trans.shared.b16 {%0,%1,%2,%3}, [%4];"
                : "=r"(b0), "=r"(b1), "=r"(b2), "=r"(b3) : "r"(addr));
            const int t0 = hf * 2;
            asm volatile(
                "mma.sync.aligned.m16n8k16.row.col.f32.f16.f16.f32 "
                "{%0,%1,%2,%3}, {%4,%5,%6,%7}, {%8,%9}, {%0,%1,%2,%3};"
                : "+f"(acc[t0][0]), "+f"(acc[t0][1]), "+f"(acc[t0][2]), "+f"(acc[t0][3])
                : "r"(a0), "r"(a1), "r"(a2), "r"(a3), "r"(b0), "r"(b1));
            asm volatile(
                "mma.sync.aligned.m16n8k16.row.col.f32.f16.f16.f32 "
                "{%0,%1,%2,%3}, {%4,%5,%6,%7}, {%8,%9}, {%0,%1,%2,%3};"
                : "+f"(acc[t0+1][0]), "+f"(acc[t0+1][1]), "+f"(acc[t0+1][2]), "+f"(acc[t0+1][3])
                : "r"(a0), "r"(a1), "r"(a2), "r"(a3), "r"(b2), "r"(b3));
        }
    }

    const int rr = lane >> 2;
    const int cc2 = (lane & 3) * 2;
#pragma unroll
    for (int t = 0; t < 4; t++) {
        const int gc = n0 + wn + t * 8 + cc2;
        const float b0f = bias[gc], b1f = bias[gc + 1];
        int gr0 = row0 + wm + rr;
        int gr1 = gr0 + 8;
        if (gr0 < N_NODES) {
            __half2 h2 = __floats2half2_rn(acc[t][0] + b0f, acc[t][1] + b1f);
            *reinterpret_cast<unsigned*>(&outp[gr0 * DIN + gc]) =
                *reinterpret_cast<unsigned*>(&h2);
        }
        if (gr1 < N_NODES) {
            __half2 h2 = __floats2half2_rn(acc[t][2] + b0f, acc[t][3] + b1f);
            *reinterpret_cast<unsigned*>(&outp[gr1 * DIN + gc]) =
                *reinterpret_cast<unsigned*>(&h2);
        }
    }
}

// ---------------------------------------------------------------------------
// CSR gather. One warp per destination node. Batch-4 edges for MLP.
// ---------------------------------------------------------------------------
__device__ __forceinline__ void edge_math(
    const uint2& kraw, const uint2& vraw, int lane,
    const float2& q0, const float2& q1,
    float& a0, float& a1, float& a2, float& a3, float& zsum)
{
    const float2 k0 = __half22float2(*reinterpret_cast<const __half2*>(&kraw.x));
    const float2 k1 = __half22float2(*reinterpret_cast<const __half2*>(&kraw.y));

    float part = k0.x * q0.x + k0.y * q0.y + k1.x * q1.x + k1.y * q1.y;
    part += __shfl_xor_sync(0xFFFFFFFFu, part, 1);
    part += __shfl_xor_sync(0xFFFFFFFFu, part, 2);

    float x = part * INV_SCALE;
    x = fminf(fmaxf(x, -5.0f), 5.0f);
    const float sc = __expf(x);

    const float2 v0 = __half22float2(*reinterpret_cast<const __half2*>(&vraw.x));
    const float2 v1 = __half22float2(*reinterpret_cast<const __half2*>(&vraw.y));

    a0 += v0.x * sc; a1 += v0.y * sc; a2 += v1.x * sc; a3 += v1.y * sc;
    zsum += sc;
}

__global__ __launch_bounds__(256)
void gather_kernel(float* __restrict__ out)
{
    const int node = (blockIdx.x * blockDim.x + threadIdx.x) >> 5;
    const int lane = threadIdx.x & 31;
    if (node >= N_NODES) return;

    const uint2 qraw = *reinterpret_cast<const uint2*>(&g_Qh[node * DIN + lane * 4]);
    const float2 q0 = __half22float2(*reinterpret_cast<const __half2*>(&qraw.x));
    const float2 q1 = __half22float2(*reinterpret_cast<const __half2*>(&qraw.y));

    const int j0 = g_off[node];
    const int j1 = g_off[node + 1];

    float a0 = 0.f, a1 = 0.f, a2 = 0.f, a3 = 0.f, zsum = 0.f;

    int j = j0;
    for (; j + 4 <= j1; j += 4) {
        const int s0 = g_esrc[j + 0];
        const int s1 = g_esrc[j + 1];
        const int s2 = g_esrc[j + 2];
        const int s3 = g_esrc[j + 3];
        const uint2 k0r = *reinterpret_cast<const uint2*>(&g_Kh[s0 * DIN + lane * 4]);
        const uint2 k1r = *reinterpret_cast<const uint2*>(&g_Kh[s1 * DIN + lane * 4]);
        const uint2 k2r = *reinterpret_cast<const uint2*>(&g_Kh[s2 * DIN + lane * 4]);
        const uint2 k3r = *reinterpret_cast<const uint2*>(&g_Kh[s3 * DIN + lane * 4]);
        const uint2 v0r = *reinterpret_cast<const uint2*>(&g_Vh[s0 * DIN + lane * 4]);
        const uint2 v1r = *reinterpret_cast<const uint2*>(&g_Vh[s1 * DIN + lane * 4]);
        const uint2 v2r = *reinterpret_cast<const uint2*>(&g_Vh[s2 * DIN + lane * 4]);
        const uint2 v3r = *reinterpret_cast<const uint2*>(&g_Vh[s3 * DIN + lane * 4]);
        edge_math(k0r, v0r, lane, q0, q1, a0, a1, a2, a3, zsum);
        edge_math(k1r, v1r, lane, q0, q1, a0, a1, a2, a3, zsum);
        edge_math(k2r, v2r, lane, q0, q1, a0, a1, a2, a3, zsum);
        edge_math(k3r, v3r, lane, q0, q1, a0, a1, a2, a3, zsum);
    }
    for (; j < j1; j++) {
        const int s = g_esrc[j];
        const uint2 kr = *reinterpret_cast<const uint2*>(&g_Kh[s * DIN + lane * 4]);
        const uint2 vr = *reinterpret_cast<const uint2*>(&g_Vh[s * DIN + lane * 4]);
        edge_math(kr, vr, lane, q0, q1, a0, a1, a2, a3, zsum);
    }

    const float zr = 1.0f / (zsum + 1e-6f);
    float4 o;
    o.x = a0 * zr; o.y = a1 * zr; o.z = a2 * zr; o.w = a3 * zr;
    *reinterpret_cast<float4*>(&out[node * DIN + lane * 4]) = o;
}

// ---------------------------------------------------------------------------
extern "C" void kernel_launch(void* const* d_in, const int* in_sizes, int n_in,
                              void* d_out, int out_size)
{
    const float* h  = (const float*)d_in[0];
    const float* Wq = (const float*)d_in[1];
    const float* bq = (const float*)d_in[2];
    const float* Wk = (const float*)d_in[3];
    const float* bk = (const float*)d_in[4];
    const float* Wv = (const float*)d_in[5];
    const float* bv = (const float*)d_in[6];
    const int*   src = (const int*)d_in[7];
    const int*   dst = (const int*)d_in[8];
    float* out = (float*)d_out;

    // fp16 conversions
    convert_h_kernel<<<(N_NODES * DIN / 4 + 255) / 256, 256>>>(h);
    convert_w_kernel<<<(3 * DIN * DIN / 4 + 255) / 256, 256>>>(Wq, Wk, Wv);

    // CSR build
    zero_deg_kernel<<<(N_NODES + 255) / 256, 256>>>();
    hist_kernel<<<1184, 256>>>(dst);
    scan_kernel<<<1, 1024>>>();          // coalesced 2-pass scan, seeds g_cur
    scatter_kernel<<<1184, 256>>>(src, dst);

    // tensor-core QKV projection
    dim3 ggrid((N_NODES + GBM - 1) / GBM, 6);
    qkv_hmma_kernel<<<ggrid, 256>>>(bq, bk, bv);

    // CSR gather: one warp per node
    gather_kernel<<<(N_NODES + 7) / 8, 256>>>(out);
}

// round 8
// speedup vs baseline: 3.7086x; 1.1340x over previous
#include <cuda_runtime.h>
#include <cuda_fp16.h>
#include <math.h>

// Problem constants (fixed by the dataset)
constexpr int N_NODES = 50000;
constexpr int E_EDGES = 800000;
constexpr int DIN     = 128;      // also H*D_HEAD
constexpr int NHEAD   = 8;
constexpr float INV_SCALE = 0.25f;   // 1/sqrt(16)

// Scratch (device globals — no allocation allowed).
__device__ __half g_hh[N_NODES * DIN];        // h in fp16
__device__ __half g_Wh[3 * DIN * DIN];        // Wq|Wk|Wv in fp16
__device__ __half g_Qh[N_NODES * DIN];
__device__ __half g_Kh[N_NODES * DIN];
__device__ __half g_Vh[N_NODES * DIN];
// CSR-by-dst structures
__device__ int g_deg[N_NODES];
__device__ int g_cur[N_NODES];
__device__ int g_off[N_NODES + 1];
__device__ int g_esrc[E_EDGES];

// ---------------------------------------------------------------------------
// Converters: fp32 -> fp16
// ---------------------------------------------------------------------------
__global__ void convert_h_kernel(const float* __restrict__ h)
{
    const int i = (blockIdx.x * blockDim.x + threadIdx.x) * 4;
    if (i >= N_NODES * DIN) return;
    float4 v = *reinterpret_cast<const float4*>(&h[i]);
    __half2 lo = __floats2half2_rn(v.x, v.y);
    __half2 hi = __floats2half2_rn(v.z, v.w);
    uint2 p;
    p.x = *reinterpret_cast<unsigned*>(&lo);
    p.y = *reinterpret_cast<unsigned*>(&hi);
    *reinterpret_cast<uint2*>(&g_hh[i]) = p;
}

__global__ void convert_w_kernel(const float* __restrict__ Wq,
                                 const float* __restrict__ Wk,
                                 const float* __restrict__ Wv)
{
    const int i = (blockIdx.x * blockDim.x + threadIdx.x) * 4;
    if (i >= 3 * DIN * DIN) return;
    const int mat = i >> 14;             // /16384
    const int off = i & 16383;
    const float* W = (mat == 0) ? Wq : (mat == 1 ? Wk : Wv);
    float4 v = *reinterpret_cast<const float4*>(&W[off]);
    __half2 lo = __floats2half2_rn(v.x, v.y);
    __half2 hi = __floats2half2_rn(v.z, v.w);
    uint2 p;
    p.x = *reinterpret_cast<unsigned*>(&lo);
    p.y = *reinterpret_cast<unsigned*>(&hi);
    *reinterpret_cast<uint2*>(&g_Wh[i]) = p;
}

// ---------------------------------------------------------------------------
// CSR build
// ---------------------------------------------------------------------------
__global__ void zero_deg_kernel()
{
    int i = blockIdx.x * blockDim.x + threadIdx.x;
    if (i < N_NODES) g_deg[i] = 0;
}

__global__ void hist_kernel(const int* __restrict__ dst)
{
    const int stride = gridDim.x * blockDim.x;
    for (int i = blockIdx.x * blockDim.x + threadIdx.x; i < E_EDGES; i += stride)
        atomicAdd(&g_deg[dst[i]], 1);
}

// Coalesced single-block scan; seeds g_cur = g_off.
__global__ __launch_bounds__(1024)
void scan_kernel()
{
    constexpr int WREG  = 1568;            // 49 * 32
    constexpr int ITERS = WREG / 32;       // 49
    __shared__ int warpTot[32];

    const int tid  = threadIdx.x;
    const int lane = tid & 31;
    const int w    = tid >> 5;
    const int base = w * WREG;

    int s = 0;
#pragma unroll
    for (int i = 0; i < ITERS; i++) {
        int idx = base + i * 32 + lane;
        if (idx < N_NODES) s += g_deg[idx];
    }
#pragma unroll
    for (int o = 16; o > 0; o >>= 1)
        s += __shfl_xor_sync(0xFFFFFFFFu, s, o);
    if (lane == 0) warpTot[w] = s;
    __syncthreads();

    if (w == 0) {
        int v = warpTot[lane];
        int p = v;
#pragma unroll
        for (int o = 1; o < 32; o <<= 1) {
            int t = __shfl_up_sync(0xFFFFFFFFu, p, o);
            if (lane >= o) p += t;
        }
        warpTot[lane] = p - v;
    }
    __syncthreads();

    int carry = warpTot[w];
#pragma unroll
    for (int i = 0; i < ITERS; i++) {
        int idx = base + i * 32 + lane;
        int v = (idx < N_NODES) ? g_deg[idx] : 0;
        int incl = v;
#pragma unroll
        for (int o = 1; o < 32; o <<= 1) {
            int t = __shfl_up_sync(0xFFFFFFFFu, incl, o);
            if (lane >= o) incl += t;
        }
        if (idx < N_NODES) {
            int e = carry + incl - v;
            g_off[idx] = e;
            g_cur[idx] = e;
        }
        carry += __shfl_sync(0xFFFFFFFFu, incl, 31);
    }
    if (tid == 0) g_off[N_NODES] = E_EDGES;
}

__global__ void scatter_kernel(const int* __restrict__ src,
                               const int* __restrict__ dst)
{
    const int stride = gridDim.x * blockDim.x;
    for (int i = blockIdx.x * blockDim.x + threadIdx.x; i < E_EDGES; i += stride) {
        const int p = atomicAdd(&g_cur[dst[i]], 1);
        g_esrc[p] = src[i];
    }
}

// ---------------------------------------------------------------------------
// Tensor-core QKV GEMM (unchanged from R7)
// ---------------------------------------------------------------------------
constexpr int GBM = 64;
constexpr int LDA = 136;
constexpr int LDB = 72;

__global__ __launch_bounds__(256)
void qkv_hmma_kernel(const float* __restrict__ bq,
                     const float* __restrict__ bk,
                     const float* __restrict__ bv)
{
    __shared__ __half sA[GBM * LDA];
    __shared__ __half sB[DIN * LDB];

    const int tid  = threadIdx.x;
    const int lane = tid & 31;
    const int wid  = tid >> 5;
    const int row0 = blockIdx.x * GBM;
    const int by   = blockIdx.y;
    const int mat  = by >> 1;
    const int n0   = (by & 1) * 64;

    const float* bias = (mat == 0) ? bq : (mat == 1 ? bk : bv);
    __half*      outp = (mat == 0) ? g_Qh : (mat == 1 ? g_Kh : g_Vh);
    const __half* Wp  = g_Wh + mat * DIN * DIN;

#pragma unroll
    for (int p = 0; p < 4; p++) {
        int c   = tid + p * 256;
        int r   = c >> 4;
        int cc  = (c & 15) << 3;
        int gr  = row0 + r;
        if (gr >= N_NODES) gr = N_NODES - 1;
        uint4 v = *reinterpret_cast<const uint4*>(&g_hh[gr * DIN + cc]);
        *reinterpret_cast<uint4*>(&sA[r * LDA + cc]) = v;
    }
#pragma unroll
    for (int p = 0; p < 4; p++) {
        int c  = tid + p * 256;
        int r  = c >> 3;
        int cc = (c & 7) << 3;
        uint4 v = *reinterpret_cast<const uint4*>(&Wp[r * DIN + n0 + cc]);
        *reinterpret_cast<uint4*>(&sB[r * LDB + cc]) = v;
    }
    __syncthreads();

    const int wm = (wid & 3) * 16;
    const int wn = (wid >> 2) * 32;

    float acc[4][4];
#pragma unroll
    for (int t = 0; t < 4; t++)
#pragma unroll
        for (int r = 0; r < 4; r++) acc[t][r] = 0.f;

    const unsigned aBase = (unsigned)__cvta_generic_to_shared(sA);
    const unsigned bBase = (unsigned)__cvta_generic_to_shared(sB);

#pragma unroll
    for (int ks = 0; ks < 8; ks++) {
        const int k0 = ks * 16;
        unsigned a0, a1, a2, a3;
        {
            unsigned addr = aBase +
                ((wm + (lane & 15)) * LDA + k0 + ((lane >> 4) << 3)) * 2;
            asm volatile(
                "ldmatrix.sync.aligned.m8n8.x4.shared.b16 {%0,%1,%2,%3}, [%4];"
                : "=r"(a0), "=r"(a1), "=r"(a2), "=r"(a3) : "r"(addr));
        }
#pragma unroll
        for (int hf = 0; hf < 2; hf++) {
            const int nw = wn + hf * 16;
            unsigned b0, b1, b2, b3;
            unsigned addr = bBase +
                ((k0 + (lane & 15)) * LDB + nw + ((lane >> 4) << 3)) * 2;
            asm volatile(
                "ldmatrix.sync.aligned.m8n8.x4.trans.shared.b16 {%0,%1,%2,%3}, [%4];"
                : "=r"(b0), "=r"(b1), "=r"(b2), "=r"(b3) : "r"(addr));
            const int t0 = hf * 2;
            asm volatile(
                "mma.sync.aligned.m16n8k16.row.col.f32.f16.f16.f32 "
                "{%0,%1,%2,%3}, {%4,%5,%6,%7}, {%8,%9}, {%0,%1,%2,%3};"
                : "+f"(acc[t0][0]), "+f"(acc[t0][1]), "+f"(acc[t0][2]), "+f"(acc[t0][3])
                : "r"(a0), "r"(a1), "r"(a2), "r"(a3), "r"(b0), "r"(b1));
            asm volatile(
                "mma.sync.aligned.m16n8k16.row.col.f32.f16.f16.f32 "
                "{%0,%1,%2,%3}, {%4,%5,%6,%7}, {%8,%9}, {%0,%1,%2,%3};"
                : "+f"(acc[t0+1][0]), "+f"(acc[t0+1][1]), "+f"(acc[t0+1][2]), "+f"(acc[t0+1][3])
                : "r"(a0), "r"(a1), "r"(a2), "r"(a3), "r"(b2), "r"(b3));
        }
    }

    const int rr = lane >> 2;
    const int cc2 = (lane & 3) * 2;
#pragma unroll
    for (int t = 0; t < 4; t++) {
        const int gc = n0 + wn + t * 8 + cc2;
        const float b0f = bias[gc], b1f = bias[gc + 1];
        int gr0 = row0 + wm + rr;
        int gr1 = gr0 + 8;
        if (gr0 < N_NODES) {
            __half2 h2 = __floats2half2_rn(acc[t][0] + b0f, acc[t][1] + b1f);
            *reinterpret_cast<unsigned*>(&outp[gr0 * DIN + gc]) =
                *reinterpret_cast<unsigned*>(&h2);
        }
        if (gr1 < N_NODES) {
            __half2 h2 = __floats2half2_rn(acc[t][2] + b0f, acc[t][3] + b1f);
            *reinterpret_cast<unsigned*>(&outp[gr1 * DIN + gc]) =
                *reinterpret_cast<unsigned*>(&h2);
        }
    }
}

// ---------------------------------------------------------------------------
// CSR gather (unchanged from R7)
// ---------------------------------------------------------------------------
__device__ __forceinline__ void edge_math(
    const uint2& kraw, const uint2& vraw, int lane,
    const float2& q0, const float2& q1,
    float& a0, float& a1, float& a2, float& a3, float& zsum)
{
    const float2 k0 = __half22float2(*reinterpret_cast<const __half2*>(&kraw.x));
    const float2 k1 = __half22float2(*reinterpret_cast<const __half2*>(&kraw.y));

    float part = k0.x * q0.x + k0.y * q0.y + k1.x * q1.x + k1.y * q1.y;
    part += __shfl_xor_sync(0xFFFFFFFFu, part, 1);
    part += __shfl_xor_sync(0xFFFFFFFFu, part, 2);

    float x = part * INV_SCALE;
    x = fminf(fmaxf(x, -5.0f), 5.0f);
    const float sc = __expf(x);

    const float2 v0 = __half22float2(*reinterpret_cast<const __half2*>(&vraw.x));
    const float2 v1 = __half22float2(*reinterpret_cast<const __half2*>(&vraw.y));

    a0 += v0.x * sc; a1 += v0.y * sc; a2 += v1.x * sc; a3 += v1.y * sc;
    zsum += sc;
}

__global__ __launch_bounds__(256)
void gather_kernel(float* __restrict__ out)
{
    const int node = (blockIdx.x * blockDim.x + threadIdx.x) >> 5;
    const int lane = threadIdx.x & 31;
    if (node >= N_NODES) return;

    const uint2 qraw = *reinterpret_cast<const uint2*>(&g_Qh[node * DIN + lane * 4]);
    const float2 q0 = __half22float2(*reinterpret_cast<const __half2*>(&qraw.x));
    const float2 q1 = __half22float2(*reinterpret_cast<const __half2*>(&qraw.y));

    const int j0 = g_off[node];
    const int j1 = g_off[node + 1];

    float a0 = 0.f, a1 = 0.f, a2 = 0.f, a3 = 0.f, zsum = 0.f;

    int j = j0;
    for (; j + 4 <= j1; j += 4) {
        const int s0 = g_esrc[j + 0];
        const int s1 = g_esrc[j + 1];
        const int s2 = g_esrc[j + 2];
        const int s3 = g_esrc[j + 3];
        const uint2 k0r = *reinterpret_cast<const uint2*>(&g_Kh[s0 * DIN + lane * 4]);
        const uint2 k1r = *reinterpret_cast<const uint2*>(&g_Kh[s1 * DIN + lane * 4]);
        const uint2 k2r = *reinterpret_cast<const uint2*>(&g_Kh[s2 * DIN + lane * 4]);
        const uint2 k3r = *reinterpret_cast<const uint2*>(&g_Kh[s3 * DIN + lane * 4]);
        const uint2 v0r = *reinterpret_cast<const uint2*>(&g_Vh[s0 * DIN + lane * 4]);
        const uint2 v1r = *reinterpret_cast<const uint2*>(&g_Vh[s1 * DIN + lane * 4]);
        const uint2 v2r = *reinterpret_cast<const uint2*>(&g_Vh[s2 * DIN + lane * 4]);
        const uint2 v3r = *reinterpret_cast<const uint2*>(&g_Vh[s3 * DIN + lane * 4]);
        edge_math(k0r, v0r, lane, q0, q1, a0, a1, a2, a3, zsum);
        edge_math(k1r, v1r, lane, q0, q1, a0, a1, a2, a3, zsum);
        edge_math(k2r, v2r, lane, q0, q1, a0, a1, a2, a3, zsum);
        edge_math(k3r, v3r, lane, q0, q1, a0, a1, a2, a3, zsum);
    }
    for (; j < j1; j++) {
        const int s = g_esrc[j];
        const uint2 kr = *reinterpret_cast<const uint2*>(&g_Kh[s * DIN + lane * 4]);
        const uint2 vr = *reinterpret_cast<const uint2*>(&g_Vh[s * DIN + lane * 4]);
        edge_math(kr, vr, lane, q0, q1, a0, a1, a2, a3, zsum);
    }

    const float zr = 1.0f / (zsum + 1e-6f);
    float4 o;
    o.x = a0 * zr; o.y = a1 * zr; o.z = a2 * zr; o.w = a3 * zr;
    *reinterpret_cast<float4*>(&out[node * DIN + lane * 4]) = o;
}

// ---------------------------------------------------------------------------
// Launch: fork CSR chain onto a side stream, join before gather.
// Stream/events are host objects created once (not device memory).
// ---------------------------------------------------------------------------
struct SideRes {
    cudaStream_t stream;
    cudaEvent_t  fork, join;
};
static SideRes make_side_res()
{
    SideRes r;
    cudaStreamCreateWithFlags(&r.stream, cudaStreamNonBlocking);
    cudaEventCreateWithFlags(&r.fork, cudaEventDisableTiming);
    cudaEventCreateWithFlags(&r.join, cudaEventDisableTiming);
    return r;
}

extern "C" void kernel_launch(void* const* d_in, const int* in_sizes, int n_in,
                              void* d_out, int out_size)
{
    static SideRes sr = make_side_res();

    const float* h  = (const float*)d_in[0];
    const float* Wq = (const float*)d_in[1];
    const float* bq = (const float*)d_in[2];
    const float* Wk = (const float*)d_in[3];
    const float* bk = (const float*)d_in[4];
    const float* Wv = (const float*)d_in[5];
    const float* bv = (const float*)d_in[6];
    const int*   src = (const int*)d_in[7];
    const int*   dst = (const int*)d_in[8];
    float* out = (float*)d_out;

    // Fork: CSR chain on side stream, concurrent with convert+GEMM chain.
    cudaEventRecord(sr.fork, 0);
    cudaStreamWaitEvent(sr.stream, sr.fork, 0);

    zero_deg_kernel<<<(N_NODES + 255) / 256, 256, 0, sr.stream>>>();
    hist_kernel<<<1184, 256, 0, sr.stream>>>(dst);
    scan_kernel<<<1, 1024, 0, sr.stream>>>();
    scatter_kernel<<<1184, 256, 0, sr.stream>>>(src, dst);
    cudaEventRecord(sr.join, sr.stream);

    // Main stream: fp16 converts + tensor-core QKV projection.
    convert_h_kernel<<<(N_NODES * DIN / 4 + 255) / 256, 256>>>(h);
    convert_w_kernel<<<(3 * DIN * DIN / 4 + 255) / 256, 256>>>(Wq, Wk, Wv);
    dim3 ggrid((N_NODES + GBM - 1) / GBM, 6);
    qkv_hmma_kernel<<<ggrid, 256>>>(bq, bk, bv);

    // Join, then gather.
    cudaStreamWaitEvent(0, sr.join, 0);
    gather_kernel<<<(N_NODES + 7) / 8, 256>>>(out);
}